// round 3
// baseline (speedup 1.0000x reference)
#include <cuda_runtime.h>
#include <cstdint>

// Problem constants (from reference: N_NODES=50000, E=800000, 128->128->64)
#define NN 50000
#define NE 800000
#define IN_CH 128
#define HID 128
#define ZD 64

// ---------------- device scratch (allocation-free per harness rules) --------
__device__ int   g_cnt[NN];
__device__ int   g_fill[NN];
__device__ int   g_rowptr[NN + 1];
__device__ float g_dinv[NN];
__device__ int   g_csr[NE];
__device__ float g_h1[(size_t)NN * HID];    // x @ W1
__device__ float g_agg1[(size_t)NN * HID];  // relu(norm-agg(h1) + b1)
__device__ float g_h2[(size_t)NN * ZD];     // agg1 @ W2

// ---------------- graph preprocessing ---------------------------------------
__global__ void init_kernel(int n) {
    int i = blockIdx.x * blockDim.x + threadIdx.x;
    if (i < n) { g_cnt[i] = 0; g_fill[i] = 0; }
}

__global__ void hist_kernel(const int* __restrict__ dst, int E) {
    int e = blockIdx.x * blockDim.x + threadIdx.x;
    if (e < E) atomicAdd(&g_cnt[dst[e]], 1);
}

__global__ void dinv_kernel(int n) {
    int i = blockIdx.x * blockDim.x + threadIdx.x;
    if (i < n) g_dinv[i] = rsqrtf((float)(g_cnt[i] + 1));  // +1 self loop
}

// single-block exclusive scan of g_cnt -> g_rowptr (warp-shuffle based)
__global__ void scan_kernel(int n) {
    __shared__ int warp_tot[32];
    __shared__ int carry_s;
    int tid = threadIdx.x, lane = tid & 31, wid = tid >> 5;
    if (tid == 0) carry_s = 0;
    __syncthreads();
    for (int base = 0; base < n; base += 1024) {
        int i = base + tid;
        int v = (i < n) ? g_cnt[i] : 0;
        int s = v;
        #pragma unroll
        for (int off = 1; off < 32; off <<= 1) {
            int t = __shfl_up_sync(0xffffffffu, s, off);
            if (lane >= off) s += t;
        }
        if (lane == 31) warp_tot[wid] = s;
        __syncthreads();
        if (wid == 0) {
            int w = warp_tot[lane];
            int ws = w;
            #pragma unroll
            for (int off = 1; off < 32; off <<= 1) {
                int t = __shfl_up_sync(0xffffffffu, ws, off);
                if (lane >= off) ws += t;
            }
            warp_tot[lane] = ws - w;  // exclusive warp offsets
        }
        __syncthreads();
        int carry = carry_s;
        int incl = s + warp_tot[wid] + carry;
        if (i < n) g_rowptr[i + 1] = incl;
        __syncthreads();              // everyone read carry_s before update
        if (tid == 1023) carry_s = incl;
        __syncthreads();
    }
    if (threadIdx.x == 0) g_rowptr[0] = 0;
}

__global__ void scatter_kernel(const int* __restrict__ src,
                               const int* __restrict__ dst, int E) {
    int e = blockIdx.x * blockDim.x + threadIdx.x;
    if (e < E) {
        int d = dst[e];
        int s = src[e];
        int pos = g_rowptr[d] + atomicAdd(&g_fill[d], 1);
        g_csr[pos] = s;
    }
}

// ---------------- GEMM: C[M,BN] = A[M,128] @ W[128,BN] ----------------------
template <int BN, int TN>
__device__ __forceinline__ void gemm_body(const float* __restrict__ A,
                                          const float* __restrict__ W,
                                          float* __restrict__ C, int M) {
    constexpr int BM = 128, BK = 16, TM = 8;
    constexpr int TCN = BN / TN;  // 16 -> 256 threads with BM/TM=16
    __shared__ float sA[BK][BM + 1];  // transposed A tile, padded
    __shared__ float sW[BK][BN];
    const int tid = threadIdx.x;
    const int tc = tid % TCN, tr = tid / TCN;
    const int row0 = blockIdx.x * BM;

    float acc[TM][TN];
    #pragma unroll
    for (int i = 0; i < TM; i++)
        #pragma unroll
        for (int j = 0; j < TN; j++) acc[i][j] = 0.f;

    for (int k0 = 0; k0 < 128; k0 += BK) {
        #pragma unroll
        for (int l = 0; l < (BM * BK) / 256; ++l) {
            int idx = tid + l * 256;
            int r = idx / BK, c = idx % BK;
            int row = row0 + r;
            sA[c][r] = (row < M) ? A[(size_t)row * 128 + k0 + c] : 0.f;
        }
        #pragma unroll
        for (int l = 0; l < (BK * BN) / 256; ++l) {
            int idx = tid + l * 256;
            int r = idx / BN, c = idx % BN;
            sW[r][c] = W[(size_t)(k0 + r) * BN + c];
        }
        __syncthreads();
        #pragma unroll
        for (int kk = 0; kk < BK; kk++) {
            float a[TM], b[TN];
            #pragma unroll
            for (int i = 0; i < TM; i++) a[i] = sA[kk][tr * TM + i];
            #pragma unroll
            for (int j = 0; j < TN; j++) b[j] = sW[kk][tc * TN + j];
            #pragma unroll
            for (int i = 0; i < TM; i++)
                #pragma unroll
                for (int j = 0; j < TN; j++) acc[i][j] += a[i] * b[j];
        }
        __syncthreads();
    }
    #pragma unroll
    for (int i = 0; i < TM; i++) {
        int row = row0 + tr * TM + i;
        if (row < M) {
            #pragma unroll
            for (int j = 0; j < TN; j++)
                C[(size_t)row * BN + tc * TN + j] = acc[i][j];
        }
    }
}

__global__ void __launch_bounds__(256) gemm1_kernel(const float* __restrict__ x,
                                                    const float* __restrict__ W1, int M) {
    gemm_body<HID, 8>(x, W1, g_h1, M);
}
__global__ void __launch_bounds__(256) gemm2_kernel(const float* __restrict__ W2, int M) {
    gemm_body<ZD, 4>(g_agg1, W2, g_h2, M);
}

// ---------------- aggregation: out[i] = act(dinv[i]*Σ_e dinv[src]*h[src] + b)
// self loop folded in as an edge with weight dinv[i].
template <int COLS, bool RELU>
__device__ __forceinline__ void agg_body(const float* __restrict__ h,
                                         const float* __restrict__ bias,
                                         float* __restrict__ out, int n) {
    int gw = (int)((blockIdx.x * blockDim.x + threadIdx.x) >> 5);
    if (gw >= n) return;
    const int lane = threadIdx.x & 31;
    constexpr int V = COLS / 32;
    const float di = g_dinv[gw];
    float acc[V];
    {
        const float* p = h + (size_t)gw * COLS + lane * V;
        if constexpr (V == 4) {
            float4 v = *(const float4*)p;
            acc[0] = di * v.x; acc[1] = di * v.y; acc[2] = di * v.z; acc[3] = di * v.w;
        } else {
            float2 v = *(const float2*)p;
            acc[0] = di * v.x; acc[1] = di * v.y;
        }
    }
    int e = g_rowptr[gw];
    const int end = g_rowptr[gw + 1];
    for (; e + 2 <= end; e += 2) {
        int s0 = __ldg(&g_csr[e]), s1 = __ldg(&g_csr[e + 1]);
        float w0 = __ldg(&g_dinv[s0]), w1 = __ldg(&g_dinv[s1]);
        const float* p0 = h + (size_t)s0 * COLS + lane * V;
        const float* p1 = h + (size_t)s1 * COLS + lane * V;
        if constexpr (V == 4) {
            float4 a = *(const float4*)p0;
            float4 b = *(const float4*)p1;
            acc[0] += w0 * a.x; acc[1] += w0 * a.y; acc[2] += w0 * a.z; acc[3] += w0 * a.w;
            acc[0] += w1 * b.x; acc[1] += w1 * b.y; acc[2] += w1 * b.z; acc[3] += w1 * b.w;
        } else {
            float2 a = *(const float2*)p0;
            float2 b = *(const float2*)p1;
            acc[0] += w0 * a.x; acc[1] += w0 * a.y;
            acc[0] += w1 * b.x; acc[1] += w1 * b.y;
        }
    }
    if (e < end) {
        int s0 = __ldg(&g_csr[e]);
        float w0 = __ldg(&g_dinv[s0]);
        const float* p0 = h + (size_t)s0 * COLS + lane * V;
        if constexpr (V == 4) {
            float4 a = *(const float4*)p0;
            acc[0] += w0 * a.x; acc[1] += w0 * a.y; acc[2] += w0 * a.z; acc[3] += w0 * a.w;
        } else {
            float2 a = *(const float2*)p0;
            acc[0] += w0 * a.x; acc[1] += w0 * a.y;
        }
    }
    #pragma unroll
    for (int v = 0; v < V; v++) {
        float r = di * acc[v] + bias[lane * V + v];
        if constexpr (RELU) r = fmaxf(r, 0.f);
        out[(size_t)gw * COLS + lane * V + v] = r;
    }
}

__global__ void __launch_bounds__(256) agg1_kernel(const float* __restrict__ b1, int n) {
    agg_body<HID, true>(g_h1, b1, g_agg1, n);
}
__global__ void __launch_bounds__(256) agg2_kernel(const float* __restrict__ b2,
                                                   float* __restrict__ out, int n) {
    agg_body<ZD, false>(g_h2, b2, out, n);
}

// ---------------- launch ----------------------------------------------------
extern "C" void kernel_launch(void* const* d_in, const int* in_sizes, int n_in,
                              void* d_out, int out_size) {
    const float* x  = (const float*)d_in[0];
    const int*   ei = (const int*)d_in[1];     // JAX default x64 disabled -> int32
    const float* W1 = (const float*)d_in[2];
    const float* b1 = (const float*)d_in[3];
    const float* W2 = (const float*)d_in[4];
    const float* b2 = (const float*)d_in[5];
    float*       out = (float*)d_out;

    const int N = in_sizes[0] / IN_CH;   // 50000
    const int E = in_sizes[1] / 2;       // 800000
    const int* src = ei;
    const int* dst = ei + E;

    const int TB = 256;
    init_kernel<<<(N + TB - 1) / TB, TB>>>(N);
    hist_kernel<<<(E + TB - 1) / TB, TB>>>(dst, E);
    dinv_kernel<<<(N + TB - 1) / TB, TB>>>(N);
    scan_kernel<<<1, 1024>>>(N);
    scatter_kernel<<<(E + TB - 1) / TB, TB>>>(src, dst, E);

    // layer 1: h1 = x @ W1 ; agg1 = relu(norm-agg(h1) + b1)
    gemm1_kernel<<<(N + 127) / 128, 256>>>(x, W1, N);
    agg1_kernel<<<((N * 32) + TB - 1) / TB, TB>>>(b1, N);

    // layer 2: h2 = agg1 @ W2 ; out = norm-agg(h2) + b2
    gemm2_kernel<<<(N + 127) / 128, 256>>>(W2, N);
    agg2_kernel<<<((N * 32) + TB - 1) / TB, TB>>>(b2, out, N);
}

// round 4
// speedup vs baseline: 1.1267x; 1.1267x over previous
#include <cuda_runtime.h>
#include <cstdint>

// Problem constants (from reference: N_NODES=50000, E=800000, 128->128->64)
#define NN 50000
#define NE 800000
#define IN_CH 128
#define HID 128
#define ZD 64
#define SCAN_B 1024
#define NB ((NN + SCAN_B - 1) / SCAN_B)   // 49 blocks

// ---------------- device scratch (allocation-free per harness rules) --------
__device__ int   g_cnt[NN];
__device__ int   g_fill[NN];
__device__ int   g_rowptr[NN + 1];
__device__ int   g_part[64];               // block partial sums (NB<=64)
__device__ float g_dinv[NN];
__device__ int   g_csr[NE];
__device__ float g_h1[(size_t)NN * HID];    // x @ W1
__device__ float g_agg1[(size_t)NN * HID];  // relu(norm-agg(h1) + b1)
__device__ float g_h2[(size_t)NN * ZD];     // agg1 @ W2

// ---------------- graph preprocessing ---------------------------------------
__global__ void init_kernel(int n) {
    int i = blockIdx.x * blockDim.x + threadIdx.x;
    if (i < n) { g_cnt[i] = 0; g_fill[i] = 0; }
}

__global__ void hist_kernel(const int* __restrict__ dst, int E) {
    int e = blockIdx.x * blockDim.x + threadIdx.x;
    if (e < E) atomicAdd(&g_cnt[dst[e]], 1);
}

// phase 1: per-block inclusive scan of g_cnt -> g_rowptr[i+1] (block-local),
// block totals -> g_part. Also computes dinv (fused).
__global__ void __launch_bounds__(SCAN_B) scan1_kernel(int n) {
    __shared__ int warp_tot[32];
    int tid = threadIdx.x, lane = tid & 31, wid = tid >> 5;
    int i = blockIdx.x * SCAN_B + tid;
    int v = (i < n) ? g_cnt[i] : 0;
    if (i < n) g_dinv[i] = rsqrtf((float)(v + 1));  // +1 self loop
    int s = v;
    #pragma unroll
    for (int off = 1; off < 32; off <<= 1) {
        int t = __shfl_up_sync(0xffffffffu, s, off);
        if (lane >= off) s += t;
    }
    if (lane == 31) warp_tot[wid] = s;
    __syncthreads();
    if (wid == 0) {
        int w = warp_tot[lane];
        int ws = w;
        #pragma unroll
        for (int off = 1; off < 32; off <<= 1) {
            int t = __shfl_up_sync(0xffffffffu, ws, off);
            if (lane >= off) ws += t;
        }
        warp_tot[lane] = ws - w;  // exclusive warp offsets
    }
    __syncthreads();
    int incl = s + warp_tot[wid];
    if (i < n) g_rowptr[i + 1] = incl;               // block-local inclusive
    if (tid == SCAN_B - 1) g_part[blockIdx.x] = incl; // block total
}

// phase 2: one warp scans NB (<=64) block totals -> exclusive offsets in g_part
__global__ void scan2_kernel(int nb) {
    int lane = threadIdx.x;  // 32 threads
    int v0 = (lane < nb) ? g_part[lane] : 0;
    int v1 = (lane + 32 < nb) ? g_part[lane + 32] : 0;
    int s0 = v0;
    #pragma unroll
    for (int off = 1; off < 32; off <<= 1) {
        int t = __shfl_up_sync(0xffffffffu, s0, off);
        if (lane >= off) s0 += t;
    }
    int tot0 = __shfl_sync(0xffffffffu, s0, 31);
    int s1 = v1;
    #pragma unroll
    for (int off = 1; off < 32; off <<= 1) {
        int t = __shfl_up_sync(0xffffffffu, s1, off);
        if (lane >= off) s1 += t;
    }
    if (lane < nb) g_part[lane] = s0 - v0;                 // exclusive
    if (lane + 32 < nb) g_part[lane + 32] = s1 - v1 + tot0;
    if (lane == 0) g_rowptr[0] = 0;
}

// phase 3: add block offsets
__global__ void __launch_bounds__(SCAN_B) scan3_kernel(int n) {
    int i = blockIdx.x * SCAN_B + threadIdx.x;
    if (i < n && blockIdx.x > 0) g_rowptr[i + 1] += g_part[blockIdx.x];
}

__global__ void scatter_kernel(const int* __restrict__ src,
                               const int* __restrict__ dst, int E) {
    int e = blockIdx.x * blockDim.x + threadIdx.x;
    if (e < E) {
        int d = dst[e];
        int s = src[e];
        int pos = g_rowptr[d] + atomicAdd(&g_fill[d], 1);
        g_csr[pos] = s;
    }
}

// ---------------- GEMM: C[M,BN] = A[M,128] @ W[128,BN] ----------------------
template <int BN, int TN>
__device__ __forceinline__ void gemm_body(const float* __restrict__ A,
                                          const float* __restrict__ W,
                                          float* __restrict__ C, int M) {
    constexpr int BM = 128, BK = 16, TM = 8;
    constexpr int TCN = BN / TN;  // 16 -> 256 threads with BM/TM=16
    __shared__ float sA[BK][BM + 1];  // transposed A tile, padded
    __shared__ float sW[BK][BN];
    const int tid = threadIdx.x;
    const int tc = tid % TCN, tr = tid / TCN;
    const int row0 = blockIdx.x * BM;

    float acc[TM][TN];
    #pragma unroll
    for (int i = 0; i < TM; i++)
        #pragma unroll
        for (int j = 0; j < TN; j++) acc[i][j] = 0.f;

    for (int k0 = 0; k0 < 128; k0 += BK) {
        #pragma unroll
        for (int l = 0; l < (BM * BK) / 256; ++l) {
            int idx = tid + l * 256;
            int r = idx / BK, c = idx % BK;
            int row = row0 + r;
            sA[c][r] = (row < M) ? A[(size_t)row * 128 + k0 + c] : 0.f;
        }
        #pragma unroll
        for (int l = 0; l < (BK * BN) / 256; ++l) {
            int idx = tid + l * 256;
            int r = idx / BN, c = idx % BN;
            sW[r][c] = W[(size_t)(k0 + r) * BN + c];
        }
        __syncthreads();
        #pragma unroll
        for (int kk = 0; kk < BK; kk++) {
            float a[TM], b[TN];
            #pragma unroll
            for (int i = 0; i < TM; i++) a[i] = sA[kk][tr * TM + i];
            #pragma unroll
            for (int j = 0; j < TN; j++) b[j] = sW[kk][tc * TN + j];
            #pragma unroll
            for (int i = 0; i < TM; i++)
                #pragma unroll
                for (int j = 0; j < TN; j++) acc[i][j] += a[i] * b[j];
        }
        __syncthreads();
    }
    #pragma unroll
    for (int i = 0; i < TM; i++) {
        int row = row0 + tr * TM + i;
        if (row < M) {
            #pragma unroll
            for (int j = 0; j < TN; j++)
                C[(size_t)row * BN + tc * TN + j] = acc[i][j];
        }
    }
}

__global__ void __launch_bounds__(256) gemm1_kernel(const float* __restrict__ x,
                                                    const float* __restrict__ W1, int M) {
    gemm_body<HID, 8>(x, W1, g_h1, M);
}
__global__ void __launch_bounds__(256) gemm2_kernel(const float* __restrict__ W2, int M) {
    gemm_body<ZD, 4>(g_agg1, W2, g_h2, M);
}

// ---------------- aggregation: out[i] = act(dinv[i]*Σ_e dinv[src]*h[src] + b)
// self loop folded in as an edge with weight dinv[i].
template <int COLS, bool RELU>
__device__ __forceinline__ void agg_body(const float* __restrict__ h,
                                         const float* __restrict__ bias,
                                         float* __restrict__ out, int n) {
    int gw = (int)((blockIdx.x * blockDim.x + threadIdx.x) >> 5);
    if (gw >= n) return;
    const int lane = threadIdx.x & 31;
    constexpr int V = COLS / 32;
    const float di = g_dinv[gw];
    float acc[V];
    {
        const float* p = h + (size_t)gw * COLS + lane * V;
        if constexpr (V == 4) {
            float4 v = *(const float4*)p;
            acc[0] = di * v.x; acc[1] = di * v.y; acc[2] = di * v.z; acc[3] = di * v.w;
        } else {
            float2 v = *(const float2*)p;
            acc[0] = di * v.x; acc[1] = di * v.y;
        }
    }
    int e = g_rowptr[gw];
    const int end = g_rowptr[gw + 1];
    for (; e + 2 <= end; e += 2) {
        int s0 = __ldg(&g_csr[e]), s1 = __ldg(&g_csr[e + 1]);
        float w0 = __ldg(&g_dinv[s0]), w1 = __ldg(&g_dinv[s1]);
        const float* p0 = h + (size_t)s0 * COLS + lane * V;
        const float* p1 = h + (size_t)s1 * COLS + lane * V;
        if constexpr (V == 4) {
            float4 a = *(const float4*)p0;
            float4 b = *(const float4*)p1;
            acc[0] += w0 * a.x; acc[1] += w0 * a.y; acc[2] += w0 * a.z; acc[3] += w0 * a.w;
            acc[0] += w1 * b.x; acc[1] += w1 * b.y; acc[2] += w1 * b.z; acc[3] += w1 * b.w;
        } else {
            float2 a = *(const float2*)p0;
            float2 b = *(const float2*)p1;
            acc[0] += w0 * a.x; acc[1] += w0 * a.y;
            acc[0] += w1 * b.x; acc[1] += w1 * b.y;
        }
    }
    if (e < end) {
        int s0 = __ldg(&g_csr[e]);
        float w0 = __ldg(&g_dinv[s0]);
        const float* p0 = h + (size_t)s0 * COLS + lane * V;
        if constexpr (V == 4) {
            float4 a = *(const float4*)p0;
            acc[0] += w0 * a.x; acc[1] += w0 * a.y; acc[2] += w0 * a.z; acc[3] += w0 * a.w;
        } else {
            float2 a = *(const float2*)p0;
            acc[0] += w0 * a.x; acc[1] += w0 * a.y;
        }
    }
    #pragma unroll
    for (int v = 0; v < V; v++) {
        float r = di * acc[v] + bias[lane * V + v];
        if constexpr (RELU) r = fmaxf(r, 0.f);
        out[(size_t)gw * COLS + lane * V + v] = r;
    }
}

__global__ void __launch_bounds__(256) agg1_kernel(const float* __restrict__ b1, int n) {
    agg_body<HID, true>(g_h1, b1, g_agg1, n);
}
__global__ void __launch_bounds__(256) agg2_kernel(const float* __restrict__ b2,
                                                   float* __restrict__ out, int n) {
    agg_body<ZD, false>(g_h2, b2, out, n);
}

// ---------------- launch ----------------------------------------------------
extern "C" void kernel_launch(void* const* d_in, const int* in_sizes, int n_in,
                              void* d_out, int out_size) {
    const float* x  = (const float*)d_in[0];
    const int*   ei = (const int*)d_in[1];     // int32 (JAX x64 disabled)
    const float* W1 = (const float*)d_in[2];
    const float* b1 = (const float*)d_in[3];
    const float* W2 = (const float*)d_in[4];
    const float* b2 = (const float*)d_in[5];
    float*       out = (float*)d_out;

    const int N = in_sizes[0] / IN_CH;   // 50000
    const int E = in_sizes[1] / 2;       // 800000
    const int* src = ei;
    const int* dst = ei + E;

    const int TB = 256;
    const int nb = (N + SCAN_B - 1) / SCAN_B;
    init_kernel<<<(N + TB - 1) / TB, TB>>>(N);
    hist_kernel<<<(E + TB - 1) / TB, TB>>>(dst, E);
    scan1_kernel<<<nb, SCAN_B>>>(N);
    scan2_kernel<<<1, 32>>>(nb);
    scan3_kernel<<<nb, SCAN_B>>>(N);
    scatter_kernel<<<(E + TB - 1) / TB, TB>>>(src, dst, E);

    // layer 1: h1 = x @ W1 ; agg1 = relu(norm-agg(h1) + b1)
    gemm1_kernel<<<(N + 127) / 128, 256>>>(x, W1, N);
    agg1_kernel<<<((N * 32) + TB - 1) / TB, TB>>>(b1, N);

    // layer 2: h2 = agg1 @ W2 ; out = norm-agg(h2) + b2
    gemm2_kernel<<<(N + 127) / 128, 256>>>(W2, N);
    agg2_kernel<<<((N * 32) + TB - 1) / TB, TB>>>(b2, out, N);
}

// round 5
// speedup vs baseline: 1.1722x; 1.0404x over previous
#include <cuda_runtime.h>
#include <cstdint>

// Problem constants (from reference: N_NODES=50000, E=800000, 128->128->64)
#define NN 50000
#define NE 800000
#define IN_CH 128
#define HID 128
#define ZD 64
#define SCAN_B 1024

// ---------------- device scratch (zero-initialized at module load) ----------
// Invariant: g_cnt and g_fill are all-zero at entry of every kernel_launch call;
// scan1 (g_cnt) and agg1 (g_fill) restore this before the call ends.
__device__ int   g_cnt[NN];
__device__ int   g_fill[NN];
__device__ int   g_rowptr[NN + 1];   // block-LOCAL inclusive scan (see row_start)
__device__ int   g_part[64];         // exclusive block offsets (<=49 blocks)
__device__ float g_dinv[NN];
__device__ int   g_csr[NE];
__device__ float g_h1[(size_t)NN * HID];    // x @ W1
__device__ float g_agg1[(size_t)NN * HID];  // relu(norm-agg(h1) + b1)
__device__ float g_h2[(size_t)NN * ZD];     // agg1 @ W2

// global exclusive row start of node i (combines local scan + block offset)
__device__ __forceinline__ int row_start(int i) {
    return (i == 0) ? 0 : (g_rowptr[i] + g_part[(i - 1) >> 10]);
}

// ---------------- graph preprocessing ---------------------------------------
__global__ void hist_kernel(const int* __restrict__ dst, int E) {
    int e = blockIdx.x * blockDim.x + threadIdx.x;
    if (e < E) atomicAdd(&g_cnt[dst[e]], 1);
}

// per-block inclusive scan of g_cnt -> g_rowptr[i+1]; block totals -> g_part;
// fused dinv; resets g_cnt for the next call.
__global__ void __launch_bounds__(SCAN_B) scan1_kernel(int n) {
    __shared__ int warp_tot[32];
    int tid = threadIdx.x, lane = tid & 31, wid = tid >> 5;
    int i = blockIdx.x * SCAN_B + tid;
    int v = 0;
    if (i < n) {
        v = g_cnt[i];
        g_cnt[i] = 0;                       // restore zero-invariant
        g_dinv[i] = rsqrtf((float)(v + 1)); // +1 self loop
    }
    int s = v;
    #pragma unroll
    for (int off = 1; off < 32; off <<= 1) {
        int t = __shfl_up_sync(0xffffffffu, s, off);
        if (lane >= off) s += t;
    }
    if (lane == 31) warp_tot[wid] = s;
    __syncthreads();
    if (wid == 0) {
        int w = warp_tot[lane];
        int ws = w;
        #pragma unroll
        for (int off = 1; off < 32; off <<= 1) {
            int t = __shfl_up_sync(0xffffffffu, ws, off);
            if (lane >= off) ws += t;
        }
        warp_tot[lane] = ws - w;  // exclusive warp offsets
    }
    __syncthreads();
    int incl = s + warp_tot[wid];
    if (i < n) g_rowptr[i + 1] = incl;                // block-local inclusive
    if (tid == SCAN_B - 1) g_part[blockIdx.x] = incl; // block total
}

// one warp scans block totals (<=64) -> exclusive offsets in g_part
__global__ void scan2_kernel(int nb) {
    int lane = threadIdx.x;  // 32 threads
    int v0 = (lane < nb) ? g_part[lane] : 0;
    int v1 = (lane + 32 < nb) ? g_part[lane + 32] : 0;
    int s0 = v0;
    #pragma unroll
    for (int off = 1; off < 32; off <<= 1) {
        int t = __shfl_up_sync(0xffffffffu, s0, off);
        if (lane >= off) s0 += t;
    }
    int tot0 = __shfl_sync(0xffffffffu, s0, 31);
    int s1 = v1;
    #pragma unroll
    for (int off = 1; off < 32; off <<= 1) {
        int t = __shfl_up_sync(0xffffffffu, s1, off);
        if (lane >= off) s1 += t;
    }
    if (lane < nb) g_part[lane] = s0 - v0;                 // exclusive
    if (lane + 32 < nb) g_part[lane + 32] = s1 - v1 + tot0;
}

__global__ void scatter_kernel(const int* __restrict__ src,
                               const int* __restrict__ dst, int E) {
    int e = blockIdx.x * blockDim.x + threadIdx.x;
    if (e < E) {
        int d = dst[e];
        int s = src[e];
        int pos = row_start(d) + atomicAdd(&g_fill[d], 1);
        g_csr[pos] = s;
    }
}

// ---------------- GEMM: C[M,BN] = A[M,128] @ W[128,BN] ----------------------
template <int BN, int TN>
__device__ __forceinline__ void gemm_body(const float* __restrict__ A,
                                          const float* __restrict__ W,
                                          float* __restrict__ C, int M) {
    constexpr int BM = 128, BK = 16, TM = 8;
    constexpr int TCN = BN / TN;  // 16 -> 256 threads with BM/TM=16
    __shared__ float sA[BK][BM + 1];  // transposed A tile, padded
    __shared__ float sW[BK][BN];
    const int tid = threadIdx.x;
    const int tc = tid % TCN, tr = tid / TCN;
    const int row0 = blockIdx.x * BM;

    float acc[TM][TN];
    #pragma unroll
    for (int i = 0; i < TM; i++)
        #pragma unroll
        for (int j = 0; j < TN; j++) acc[i][j] = 0.f;

    for (int k0 = 0; k0 < 128; k0 += BK) {
        #pragma unroll
        for (int l = 0; l < (BM * BK) / 256; ++l) {
            int idx = tid + l * 256;
            int r = idx / BK, c = idx % BK;
            int row = row0 + r;
            sA[c][r] = (row < M) ? A[(size_t)row * 128 + k0 + c] : 0.f;
        }
        #pragma unroll
        for (int l = 0; l < (BK * BN) / 256; ++l) {
            int idx = tid + l * 256;
            int r = idx / BN, c = idx % BN;
            sW[r][c] = W[(size_t)(k0 + r) * BN + c];
        }
        __syncthreads();
        #pragma unroll
        for (int kk = 0; kk < BK; kk++) {
            float a[TM], b[TN];
            #pragma unroll
            for (int i = 0; i < TM; i++) a[i] = sA[kk][tr * TM + i];
            #pragma unroll
            for (int j = 0; j < TN; j++) b[j] = sW[kk][tc * TN + j];
            #pragma unroll
            for (int i = 0; i < TM; i++)
                #pragma unroll
                for (int j = 0; j < TN; j++) acc[i][j] += a[i] * b[j];
        }
        __syncthreads();
    }
    #pragma unroll
    for (int i = 0; i < TM; i++) {
        int row = row0 + tr * TM + i;
        if (row < M) {
            #pragma unroll
            for (int j = 0; j < TN; j++)
                C[(size_t)row * BN + tc * TN + j] = acc[i][j];
        }
    }
}

__global__ void __launch_bounds__(256) gemm1_kernel(const float* __restrict__ x,
                                                    const float* __restrict__ W1, int M) {
    gemm_body<HID, 8>(x, W1, g_h1, M);
}
__global__ void __launch_bounds__(256) gemm2_kernel(const float* __restrict__ W2, int M) {
    gemm_body<ZD, 4>(g_agg1, W2, g_h2, M);
}

// ---------------- aggregation: out[i] = act(dinv[i]*Σ_e dinv[src]*h[src] + b)
// self loop folded in as weight dinv[i].
__global__ void __launch_bounds__(256) agg1_kernel(const float* __restrict__ b1, int n) {
    int gw = (int)((blockIdx.x * blockDim.x + threadIdx.x) >> 5);
    if (gw >= n) return;
    const int lane = threadIdx.x & 31;
    if (lane == 0) g_fill[gw] = 0;          // restore zero-invariant
    const float di = g_dinv[gw];
    float ax, ay, az, aw;
    {
        float4 v = *((const float4*)(g_h1 + (size_t)gw * HID) + lane);
        ax = di * v.x; ay = di * v.y; az = di * v.z; aw = di * v.w;
    }
    int e = row_start(gw);
    const int end = row_start(gw + 1);
    for (; e + 4 <= end; e += 4) {
        int s0 = __ldg(&g_csr[e]),     s1 = __ldg(&g_csr[e + 1]);
        int s2 = __ldg(&g_csr[e + 2]), s3 = __ldg(&g_csr[e + 3]);
        float w0 = __ldg(&g_dinv[s0]), w1 = __ldg(&g_dinv[s1]);
        float w2 = __ldg(&g_dinv[s2]), w3 = __ldg(&g_dinv[s3]);
        float4 a = *((const float4*)(g_h1 + (size_t)s0 * HID) + lane);
        float4 b = *((const float4*)(g_h1 + (size_t)s1 * HID) + lane);
        float4 c = *((const float4*)(g_h1 + (size_t)s2 * HID) + lane);
        float4 d = *((const float4*)(g_h1 + (size_t)s3 * HID) + lane);
        ax += w0 * a.x; ay += w0 * a.y; az += w0 * a.z; aw += w0 * a.w;
        ax += w1 * b.x; ay += w1 * b.y; az += w1 * b.z; aw += w1 * b.w;
        ax += w2 * c.x; ay += w2 * c.y; az += w2 * c.z; aw += w2 * c.w;
        ax += w3 * d.x; ay += w3 * d.y; az += w3 * d.z; aw += w3 * d.w;
    }
    for (; e < end; ++e) {
        int s0 = __ldg(&g_csr[e]);
        float w0 = __ldg(&g_dinv[s0]);
        float4 a = *((const float4*)(g_h1 + (size_t)s0 * HID) + lane);
        ax += w0 * a.x; ay += w0 * a.y; az += w0 * a.z; aw += w0 * a.w;
    }
    float4 bb = *((const float4*)b1 + lane);
    float4 r;
    r.x = fmaxf(di * ax + bb.x, 0.f);
    r.y = fmaxf(di * ay + bb.y, 0.f);
    r.z = fmaxf(di * az + bb.z, 0.f);
    r.w = fmaxf(di * aw + bb.w, 0.f);
    *((float4*)(g_agg1 + (size_t)gw * HID) + lane) = r;
}

__global__ void __launch_bounds__(256) agg2_kernel(const float* __restrict__ b2,
                                                   float* __restrict__ out, int n) {
    int gw = (int)((blockIdx.x * blockDim.x + threadIdx.x) >> 5);
    if (gw >= n) return;
    const int lane = threadIdx.x & 31;
    const float di = g_dinv[gw];
    float ax, ay;
    {
        float2 v = *((const float2*)(g_h2 + (size_t)gw * ZD) + lane);
        ax = di * v.x; ay = di * v.y;
    }
    int e = row_start(gw);
    const int end = row_start(gw + 1);
    for (; e + 4 <= end; e += 4) {
        int s0 = __ldg(&g_csr[e]),     s1 = __ldg(&g_csr[e + 1]);
        int s2 = __ldg(&g_csr[e + 2]), s3 = __ldg(&g_csr[e + 3]);
        float w0 = __ldg(&g_dinv[s0]), w1 = __ldg(&g_dinv[s1]);
        float w2 = __ldg(&g_dinv[s2]), w3 = __ldg(&g_dinv[s3]);
        float2 a = *((const float2*)(g_h2 + (size_t)s0 * ZD) + lane);
        float2 b = *((const float2*)(g_h2 + (size_t)s1 * ZD) + lane);
        float2 c = *((const float2*)(g_h2 + (size_t)s2 * ZD) + lane);
        float2 d = *((const float2*)(g_h2 + (size_t)s3 * ZD) + lane);
        ax += w0 * a.x; ay += w0 * a.y;
        ax += w1 * b.x; ay += w1 * b.y;
        ax += w2 * c.x; ay += w2 * c.y;
        ax += w3 * d.x; ay += w3 * d.y;
    }
    for (; e < end; ++e) {
        int s0 = __ldg(&g_csr[e]);
        float w0 = __ldg(&g_dinv[s0]);
        float2 a = *((const float2*)(g_h2 + (size_t)s0 * ZD) + lane);
        ax += w0 * a.x; ay += w0 * a.y;
    }
    float2 bb = *((const float2*)b2 + lane);
    float2 r;
    r.x = di * ax + bb.x;
    r.y = di * ay + bb.y;
    *((float2*)(out + (size_t)gw * ZD) + lane) = r;
}

// ---------------- launch ----------------------------------------------------
extern "C" void kernel_launch(void* const* d_in, const int* in_sizes, int n_in,
                              void* d_out, int out_size) {
    const float* x  = (const float*)d_in[0];
    const int*   ei = (const int*)d_in[1];     // int32 (JAX x64 disabled)
    const float* W1 = (const float*)d_in[2];
    const float* b1 = (const float*)d_in[3];
    const float* W2 = (const float*)d_in[4];
    const float* b2 = (const float*)d_in[5];
    float*       out = (float*)d_out;

    const int N = in_sizes[0] / IN_CH;   // 50000
    const int E = in_sizes[1] / 2;       // 800000
    const int* src = ei;
    const int* dst = ei + E;

    const int TB = 256;
    const int nb = (N + SCAN_B - 1) / SCAN_B;
    hist_kernel<<<(E + TB - 1) / TB, TB>>>(dst, E);            // 0
    scan1_kernel<<<nb, SCAN_B>>>(N);                           // 1
    scan2_kernel<<<1, 32>>>(nb);                               // 2
    scatter_kernel<<<(E + TB - 1) / TB, TB>>>(src, dst, E);    // 3

    gemm1_kernel<<<(N + 127) / 128, 256>>>(x, W1, N);          // 4
    agg1_kernel<<<((N * 32) + TB - 1) / TB, TB>>>(b1, N);      // 5 <- ncu slot
    gemm2_kernel<<<(N + 127) / 128, 256>>>(W2, N);             // 6
    agg2_kernel<<<((N * 32) + TB - 1) / TB, TB>>>(b2, out, N); // 7
}

// round 6
// speedup vs baseline: 1.3932x; 1.1885x over previous
#include <cuda_runtime.h>
#include <cuda_fp16.h>
#include <cstdint>

// Problem constants (N_NODES=50000, E=800000, 128->128->64)
#define NN 50000
#define NE 800000
#define IN_CH 128
#define HID 128
#define ZD 64
#define SCAN_B 1024

// ---------------- device scratch (zero-initialized at module load) ----------
// Invariant: g_cnt and g_fill are all-zero at entry of every kernel_launch call;
// scan1 (g_cnt) and agg1 (g_fill) restore this before the call ends.
__device__ int    g_cnt[NN];
__device__ int    g_fill[NN];
__device__ int    g_rowptr[NN + 1];  // block-LOCAL inclusive scan (see row_start)
__device__ int    g_part[64];        // exclusive block offsets (<=49 blocks)
__device__ float  g_dinv[NN];
__device__ int    g_csr[NE];
__device__ __half g_h1[(size_t)NN * HID];   // x @ W1  (fp16)
__device__ float  g_agg1[(size_t)NN * HID]; // relu(norm-agg(h1) + b1)
__device__ __half g_h2[(size_t)NN * ZD];    // agg1 @ W2 (fp16)

// global exclusive row start of node i (combines local scan + block offset)
__device__ __forceinline__ int row_start(int i) {
    return (i == 0) ? 0 : (g_rowptr[i] + g_part[(i - 1) >> 10]);
}

// ---------------- graph preprocessing ---------------------------------------
__global__ void hist_kernel(const int* __restrict__ dst, int E2) {
    int e = blockIdx.x * blockDim.x + threadIdx.x;
    if (e < E2) {
        int2 d = ((const int2*)dst)[e];
        atomicAdd(&g_cnt[d.x], 1);
        atomicAdd(&g_cnt[d.y], 1);
    }
}

// per-block inclusive scan of g_cnt -> g_rowptr[i+1]; block totals -> g_part;
// fused dinv; resets g_cnt for the next call.
__global__ void __launch_bounds__(SCAN_B) scan1_kernel(int n) {
    __shared__ int warp_tot[32];
    int tid = threadIdx.x, lane = tid & 31, wid = tid >> 5;
    int i = blockIdx.x * SCAN_B + tid;
    int v = 0;
    if (i < n) {
        v = g_cnt[i];
        g_cnt[i] = 0;                       // restore zero-invariant
        g_dinv[i] = rsqrtf((float)(v + 1)); // +1 self loop
    }
    int s = v;
    #pragma unroll
    for (int off = 1; off < 32; off <<= 1) {
        int t = __shfl_up_sync(0xffffffffu, s, off);
        if (lane >= off) s += t;
    }
    if (lane == 31) warp_tot[wid] = s;
    __syncthreads();
    if (wid == 0) {
        int w = warp_tot[lane];
        int ws = w;
        #pragma unroll
        for (int off = 1; off < 32; off <<= 1) {
            int t = __shfl_up_sync(0xffffffffu, ws, off);
            if (lane >= off) ws += t;
        }
        warp_tot[lane] = ws - w;  // exclusive warp offsets
    }
    __syncthreads();
    int incl = s + warp_tot[wid];
    if (i < n) g_rowptr[i + 1] = incl;                // block-local inclusive
    if (tid == SCAN_B - 1) g_part[blockIdx.x] = incl; // block total
}

// one warp scans block totals (<=64) -> exclusive offsets in g_part
__global__ void scan2_kernel(int nb) {
    int lane = threadIdx.x;  // 32 threads
    int v0 = (lane < nb) ? g_part[lane] : 0;
    int v1 = (lane + 32 < nb) ? g_part[lane + 32] : 0;
    int s0 = v0;
    #pragma unroll
    for (int off = 1; off < 32; off <<= 1) {
        int t = __shfl_up_sync(0xffffffffu, s0, off);
        if (lane >= off) s0 += t;
    }
    int tot0 = __shfl_sync(0xffffffffu, s0, 31);
    int s1 = v1;
    #pragma unroll
    for (int off = 1; off < 32; off <<= 1) {
        int t = __shfl_up_sync(0xffffffffu, s1, off);
        if (lane >= off) s1 += t;
    }
    if (lane < nb) g_part[lane] = s0 - v0;                 // exclusive
    if (lane + 32 < nb) g_part[lane + 32] = s1 - v1 + tot0;
}

__global__ void scatter_kernel(const int* __restrict__ src,
                               const int* __restrict__ dst, int E2) {
    int e = blockIdx.x * blockDim.x + threadIdx.x;
    if (e < E2) {
        int2 d = ((const int2*)dst)[e];
        int2 s = ((const int2*)src)[e];
        int p0 = row_start(d.x) + atomicAdd(&g_fill[d.x], 1);
        g_csr[p0] = s.x;
        int p1 = row_start(d.y) + atomicAdd(&g_fill[d.y], 1);
        g_csr[p1] = s.y;
    }
}

// ---------------- GEMM: C[M,BN] = A[M,128] @ W[128,BN], fp16 output ---------
template <int BN, int TN>
__device__ __forceinline__ void gemm_body_h(const float* __restrict__ A,
                                            const float* __restrict__ W,
                                            __half* __restrict__ C, int M) {
    constexpr int BM = 128, BK = 16, TM = 8;
    constexpr int TCN = BN / TN;
    __shared__ float sA[BK][BM + 1];
    __shared__ float sW[BK][BN];
    const int tid = threadIdx.x;
    const int tc = tid % TCN, tr = tid / TCN;
    const int row0 = blockIdx.x * BM;

    float acc[TM][TN];
    #pragma unroll
    for (int i = 0; i < TM; i++)
        #pragma unroll
        for (int j = 0; j < TN; j++) acc[i][j] = 0.f;

    for (int k0 = 0; k0 < 128; k0 += BK) {
        #pragma unroll
        for (int l = 0; l < (BM * BK) / 256; ++l) {
            int idx = tid + l * 256;
            int r = idx / BK, c = idx % BK;
            int row = row0 + r;
            sA[c][r] = (row < M) ? A[(size_t)row * 128 + k0 + c] : 0.f;
        }
        #pragma unroll
        for (int l = 0; l < (BK * BN) / 256; ++l) {
            int idx = tid + l * 256;
            int r = idx / BN, c = idx % BN;
            sW[r][c] = W[(size_t)(k0 + r) * BN + c];
        }
        __syncthreads();
        #pragma unroll
        for (int kk = 0; kk < BK; kk++) {
            float a[TM], b[TN];
            #pragma unroll
            for (int i = 0; i < TM; i++) a[i] = sA[kk][tr * TM + i];
            #pragma unroll
            for (int j = 0; j < TN; j++) b[j] = sW[kk][tc * TN + j];
            #pragma unroll
            for (int i = 0; i < TM; i++)
                #pragma unroll
                for (int j = 0; j < TN; j++) acc[i][j] += a[i] * b[j];
        }
        __syncthreads();
    }
    #pragma unroll
    for (int i = 0; i < TM; i++) {
        int row = row0 + tr * TM + i;
        if (row < M) {
            #pragma unroll
            for (int j = 0; j < TN; j += 2) {
                __half2 h = __floats2half2_rn(acc[i][j], acc[i][j + 1]);
                *(__half2*)(C + (size_t)row * BN + tc * TN + j) = h;
            }
        }
    }
}

__global__ void __launch_bounds__(256) gemm1_kernel(const float* __restrict__ x,
                                                    const float* __restrict__ W1, int M) {
    gemm_body_h<HID, 8>(x, W1, g_h1, M);
}
__global__ void __launch_bounds__(256) gemm2_kernel(const float* __restrict__ W2, int M) {
    gemm_body_h<ZD, 4>(g_agg1, W2, g_h2, M);
}

// ---------------- aggregation helpers ----------------------------------------
__device__ __forceinline__ float4 ldh4(const __half* rowbase, int lane) {
    uint2 u = __ldg((const uint2*)rowbase + lane);
    float2 f0 = __half22float2(*(__half2*)&u.x);
    float2 f1 = __half22float2(*(__half2*)&u.y);
    return make_float4(f0.x, f0.y, f1.x, f1.y);
}
__device__ __forceinline__ float2 ldh2(const __half* rowbase, int lane) {
    unsigned u = __ldg((const unsigned*)rowbase + lane);
    return __half22float2(*(__half2*)&u);
}

// out[i] = act(dinv[i] * sum_e dinv[src]*h[src] + b); self loop weight dinv[i].
__global__ void __launch_bounds__(256) agg1_kernel(const float* __restrict__ b1, int n) {
    int gw = (int)((blockIdx.x * blockDim.x + threadIdx.x) >> 5);
    if (gw >= n) return;
    const int lane = threadIdx.x & 31;
    if (lane == 0) g_fill[gw] = 0;          // restore zero-invariant
    const float di = g_dinv[gw];
    float ax, ay, az, aw;
    {
        float4 v = ldh4(g_h1 + (size_t)gw * HID, lane);
        ax = di * v.x; ay = di * v.y; az = di * v.z; aw = di * v.w;
    }
    int e = row_start(gw);
    const int end = row_start(gw + 1);
    for (; e + 4 <= end; e += 4) {
        int s0 = __ldg(&g_csr[e]),     s1 = __ldg(&g_csr[e + 1]);
        int s2 = __ldg(&g_csr[e + 2]), s3 = __ldg(&g_csr[e + 3]);
        float w0 = __ldg(&g_dinv[s0]), w1 = __ldg(&g_dinv[s1]);
        float w2 = __ldg(&g_dinv[s2]), w3 = __ldg(&g_dinv[s3]);
        float4 a = ldh4(g_h1 + (size_t)s0 * HID, lane);
        float4 b = ldh4(g_h1 + (size_t)s1 * HID, lane);
        float4 c = ldh4(g_h1 + (size_t)s2 * HID, lane);
        float4 d = ldh4(g_h1 + (size_t)s3 * HID, lane);
        ax += w0 * a.x; ay += w0 * a.y; az += w0 * a.z; aw += w0 * a.w;
        ax += w1 * b.x; ay += w1 * b.y; az += w1 * b.z; aw += w1 * b.w;
        ax += w2 * c.x; ay += w2 * c.y; az += w2 * c.z; aw += w2 * c.w;
        ax += w3 * d.x; ay += w3 * d.y; az += w3 * d.z; aw += w3 * d.w;
    }
    for (; e < end; ++e) {
        int s0 = __ldg(&g_csr[e]);
        float w0 = __ldg(&g_dinv[s0]);
        float4 a = ldh4(g_h1 + (size_t)s0 * HID, lane);
        ax += w0 * a.x; ay += w0 * a.y; az += w0 * a.z; aw += w0 * a.w;
    }
    float4 bb = *((const float4*)b1 + lane);
    float4 r;
    r.x = fmaxf(di * ax + bb.x, 0.f);
    r.y = fmaxf(di * ay + bb.y, 0.f);
    r.z = fmaxf(di * az + bb.z, 0.f);
    r.w = fmaxf(di * aw + bb.w, 0.f);
    *((float4*)(g_agg1 + (size_t)gw * HID) + lane) = r;
}

__global__ void __launch_bounds__(256) agg2_kernel(const float* __restrict__ b2,
                                                   float* __restrict__ out, int n) {
    int gw = (int)((blockIdx.x * blockDim.x + threadIdx.x) >> 5);
    if (gw >= n) return;
    const int lane = threadIdx.x & 31;
    const float di = g_dinv[gw];
    float ax, ay;
    {
        float2 v = ldh2(g_h2 + (size_t)gw * ZD, lane);
        ax = di * v.x; ay = di * v.y;
    }
    int e = row_start(gw);
    const int end = row_start(gw + 1);
    for (; e + 4 <= end; e += 4) {
        int s0 = __ldg(&g_csr[e]),     s1 = __ldg(&g_csr[e + 1]);
        int s2 = __ldg(&g_csr[e + 2]), s3 = __ldg(&g_csr[e + 3]);
        float w0 = __ldg(&g_dinv[s0]), w1 = __ldg(&g_dinv[s1]);
        float w2 = __ldg(&g_dinv[s2]), w3 = __ldg(&g_dinv[s3]);
        float2 a = ldh2(g_h2 + (size_t)s0 * ZD, lane);
        float2 b = ldh2(g_h2 + (size_t)s1 * ZD, lane);
        float2 c = ldh2(g_h2 + (size_t)s2 * ZD, lane);
        float2 d = ldh2(g_h2 + (size_t)s3 * ZD, lane);
        ax += w0 * a.x; ay += w0 * a.y;
        ax += w1 * b.x; ay += w1 * b.y;
        ax += w2 * c.x; ay += w2 * c.y;
        ax += w3 * d.x; ay += w3 * d.y;
    }
    for (; e < end; ++e) {
        int s0 = __ldg(&g_csr[e]);
        float w0 = __ldg(&g_dinv[s0]);
        float2 a = ldh2(g_h2 + (size_t)s0 * ZD, lane);
        ax += w0 * a.x; ay += w0 * a.y;
    }
    float2 bb = *((const float2*)b2 + lane);
    float2 r;
    r.x = di * ax + bb.x;
    r.y = di * ay + bb.y;
    *((float2*)(out + (size_t)gw * ZD) + lane) = r;
}

// ---------------- launch ----------------------------------------------------
extern "C" void kernel_launch(void* const* d_in, const int* in_sizes, int n_in,
                              void* d_out, int out_size) {
    const float* x  = (const float*)d_in[0];
    const int*   ei = (const int*)d_in[1];     // int32
    const float* W1 = (const float*)d_in[2];
    const float* b1 = (const float*)d_in[3];
    const float* W2 = (const float*)d_in[4];
    const float* b2 = (const float*)d_in[5];
    float*       out = (float*)d_out;

    const int N = in_sizes[0] / IN_CH;   // 50000
    const int E = in_sizes[1] / 2;       // 800000
    const int E2 = E / 2;                // edges processed 2/thread
    const int* src = ei;
    const int* dst = ei + E;

    const int TB = 256;
    const int nb = (N + SCAN_B - 1) / SCAN_B;
    hist_kernel<<<(E2 + TB - 1) / TB, TB>>>(dst, E2);          // 0
    scan1_kernel<<<nb, SCAN_B>>>(N);                           // 1
    scan2_kernel<<<1, 32>>>(nb);                               // 2
    gemm1_kernel<<<(N + 127) / 128, 256>>>(x, W1, N);          // 3 <- ncu slot
    scatter_kernel<<<(E2 + TB - 1) / TB, TB>>>(src, dst, E2);  // 4
    agg1_kernel<<<((N * 32) + TB - 1) / TB, TB>>>(b1, N);      // 5
    gemm2_kernel<<<(N + 127) / 128, 256>>>(W2, N);             // 6
    agg2_kernel<<<((N * 32) + TB - 1) / TB, TB>>>(b2, out, N); // 7
}

// round 7
// speedup vs baseline: 2.1478x; 1.5416x over previous
#include <cuda_runtime.h>
#include <cuda_fp16.h>
#include <cstdint>

// Problem constants (N_NODES=50000, E=800000, 128->128->64)
#define NN 50000
#define NE 800000
#define IN_CH 128
#define HID 128
#define ZD 64
#define SCAN_B 1024

// ---------------- device scratch (zero-initialized at module load) ----------
// Invariant: g_cnt and g_fill are all-zero at entry of every kernel_launch call;
// scan1 (g_cnt) and agg1 (g_fill) restore this before the call ends.
__device__ int    g_cnt[NN];
__device__ int    g_fill[NN];
__device__ int    g_rowptr[NN + 1];  // block-LOCAL inclusive scan (see row_start)
__device__ int    g_part[64];        // exclusive block offsets (<=49 blocks)
__device__ float  g_dinv[NN];
__device__ int    g_csr[NE];
__device__ __half g_h1[(size_t)NN * HID];   // x @ W1  (fp16)
__device__ float  g_agg1[(size_t)NN * HID]; // relu(norm-agg(h1) + b1)
__device__ __half g_h2[(size_t)NN * ZD];    // agg1 @ W2 (fp16)

__device__ __forceinline__ int row_start(int i) {
    return (i == 0) ? 0 : (g_rowptr[i] + g_part[(i - 1) >> 10]);
}

// ---------------- graph preprocessing ---------------------------------------
__global__ void hist_kernel(const int* __restrict__ dst, int E2) {
    int e = blockIdx.x * blockDim.x + threadIdx.x;
    if (e < E2) {
        int2 d = ((const int2*)dst)[e];
        atomicAdd(&g_cnt[d.x], 1);
        atomicAdd(&g_cnt[d.y], 1);
    }
}

__global__ void __launch_bounds__(SCAN_B) scan1_kernel(int n) {
    __shared__ int warp_tot[32];
    int tid = threadIdx.x, lane = tid & 31, wid = tid >> 5;
    int i = blockIdx.x * SCAN_B + tid;
    int v = 0;
    if (i < n) {
        v = g_cnt[i];
        g_cnt[i] = 0;                       // restore zero-invariant
        g_dinv[i] = rsqrtf((float)(v + 1)); // +1 self loop
    }
    int s = v;
    #pragma unroll
    for (int off = 1; off < 32; off <<= 1) {
        int t = __shfl_up_sync(0xffffffffu, s, off);
        if (lane >= off) s += t;
    }
    if (lane == 31) warp_tot[wid] = s;
    __syncthreads();
    if (wid == 0) {
        int w = warp_tot[lane];
        int ws = w;
        #pragma unroll
        for (int off = 1; off < 32; off <<= 1) {
            int t = __shfl_up_sync(0xffffffffu, ws, off);
            if (lane >= off) ws += t;
        }
        warp_tot[lane] = ws - w;
    }
    __syncthreads();
    int incl = s + warp_tot[wid];
    if (i < n) g_rowptr[i + 1] = incl;
    if (tid == SCAN_B - 1) g_part[blockIdx.x] = incl;
}

__global__ void scan2_kernel(int nb) {
    int lane = threadIdx.x;  // 32 threads
    int v0 = (lane < nb) ? g_part[lane] : 0;
    int v1 = (lane + 32 < nb) ? g_part[lane + 32] : 0;
    int s0 = v0;
    #pragma unroll
    for (int off = 1; off < 32; off <<= 1) {
        int t = __shfl_up_sync(0xffffffffu, s0, off);
        if (lane >= off) s0 += t;
    }
    int tot0 = __shfl_sync(0xffffffffu, s0, 31);
    int s1 = v1;
    #pragma unroll
    for (int off = 1; off < 32; off <<= 1) {
        int t = __shfl_up_sync(0xffffffffu, s1, off);
        if (lane >= off) s1 += t;
    }
    if (lane < nb) g_part[lane] = s0 - v0;
    if (lane + 32 < nb) g_part[lane + 32] = s1 - v1 + tot0;
}

__global__ void scatter_kernel(const int* __restrict__ src,
                               const int* __restrict__ dst, int E2) {
    int e = blockIdx.x * blockDim.x + threadIdx.x;
    if (e < E2) {
        int2 d = ((const int2*)dst)[e];
        int2 s = ((const int2*)src)[e];
        int p0 = row_start(d.x) + atomicAdd(&g_fill[d.x], 1);
        g_csr[p0] = s.x;
        int p1 = row_start(d.y) + atomicAdd(&g_fill[d.y], 1);
        g_csr[p1] = s.y;
    }
}

// ---------------- tensor-core GEMM: C[M,BN] = A[M,128] @ W[128,BN] ----------
__device__ __forceinline__ uint32_t f2h2(float2 v) {
    __half2 h = __floats2half2_rn(v.x, v.y);
    return *(uint32_t*)&h;
}
__device__ __forceinline__ void ldmx4t(uint32_t* r, uint32_t addr) {
    asm volatile("ldmatrix.sync.aligned.m8n8.x4.trans.shared.b16 {%0,%1,%2,%3}, [%4];"
                 : "=r"(r[0]), "=r"(r[1]), "=r"(r[2]), "=r"(r[3]) : "r"(addr));
}
__device__ __forceinline__ void mma16816(float* c, const uint32_t* a,
                                         uint32_t b0, uint32_t b1) {
    asm volatile("mma.sync.aligned.m16n8k16.row.col.f32.f16.f16.f32 "
                 "{%0,%1,%2,%3}, {%4,%5,%6,%7}, {%8,%9}, {%0,%1,%2,%3};"
                 : "+f"(c[0]), "+f"(c[1]), "+f"(c[2]), "+f"(c[3])
                 : "r"(a[0]), "r"(a[1]), "r"(a[2]), "r"(a[3]), "r"(b0), "r"(b1));
}

// SRC=0: A=param (x), C=g_h1 ; SRC=1: A=g_agg1, C=g_h2
template <int BN, int SRC>
__global__ void __launch_bounds__(256) gemm_mma_kernel(const float* __restrict__ Ain,
                                                       const float* __restrict__ W, int M) {
    constexpr int SW = BN + 8;   // half stride, row = (BN+8)*2 bytes -> ldmatrix conflict-free
    __shared__ __half sW[128 * SW];
    const float* A;
    __half* C;
    if constexpr (SRC == 0) { A = Ain; C = g_h1; } else { A = g_agg1; C = g_h2; }

    const int tid = threadIdx.x, lane = tid & 31, w = tid >> 5;

    // stage W (fp32 -> fp16) into padded smem
    constexpr int C2 = BN / 2;
    for (int idx = tid; idx < 128 * C2; idx += 256) {
        int r = idx / C2, c2 = idx % C2;
        float2 v = *(const float2*)(W + r * BN + c2 * 2);
        *(__half2*)(sW + r * SW + c2 * 2) = __floats2half2_rn(v.x, v.y);
    }
    __syncthreads();

    const int m0 = blockIdx.x * 128 + w * 16;
    const int ra = m0 + (lane >> 2), rb = ra + 8;
    const int ca = (lane & 3) * 2;

    // load all 8 A fragments (m16k16 each) straight from global, cvt to fp16
    uint32_t af[8][4];
    const float2 z2 = make_float2(0.f, 0.f);
    #pragma unroll
    for (int kk = 0; kk < 8; kk++) {
        int k0 = kk * 16 + ca;
        float2 v0 = (ra < M) ? *(const float2*)(A + (size_t)ra * 128 + k0) : z2;
        float2 v1 = (rb < M) ? *(const float2*)(A + (size_t)rb * 128 + k0) : z2;
        float2 v2 = (ra < M) ? *(const float2*)(A + (size_t)ra * 128 + k0 + 8) : z2;
        float2 v3 = (rb < M) ? *(const float2*)(A + (size_t)rb * 128 + k0 + 8) : z2;
        af[kk][0] = f2h2(v0); af[kk][1] = f2h2(v1);
        af[kk][2] = f2h2(v2); af[kk][3] = f2h2(v3);
    }

    uint32_t swbase = (uint32_t)__cvta_generic_to_shared(sW);
    constexpr int NT2 = BN / 16;
    float acc[NT2][2][4];
    #pragma unroll
    for (int i = 0; i < NT2; i++)
        #pragma unroll
        for (int h = 0; h < 2; h++)
            #pragma unroll
            for (int j = 0; j < 4; j++) acc[i][h][j] = 0.f;

    #pragma unroll
    for (int nt2 = 0; nt2 < NT2; nt2++) {
        #pragma unroll
        for (int kk = 0; kk < 8; kk++) {
            uint32_t b[4];
            uint32_t addr = swbase +
                (uint32_t)(((kk * 16 + (lane & 15)) * SW + nt2 * 16 + 8 * (lane >> 4)) * 2);
            ldmx4t(b, addr);
            mma16816(acc[nt2][0], af[kk], b[0], b[1]);
            mma16816(acc[nt2][1], af[kk], b[2], b[3]);
        }
    }

    // epilogue: fp32 accum -> fp16 C
    #pragma unroll
    for (int nt2 = 0; nt2 < NT2; nt2++) {
        #pragma unroll
        for (int h = 0; h < 2; h++) {
            int col = nt2 * 16 + h * 8 + ca;
            float* c = acc[nt2][h];
            if (ra < M) *(__half2*)(C + (size_t)ra * BN + col) = __floats2half2_rn(c[0], c[1]);
            if (rb < M) *(__half2*)(C + (size_t)rb * BN + col) = __floats2half2_rn(c[2], c[3]);
        }
    }
}

// ---------------- aggregation helpers ----------------------------------------
__device__ __forceinline__ float4 ldh4(const __half* rowbase, int lane) {
    uint2 u = __ldg((const uint2*)rowbase + lane);
    float2 f0 = __half22float2(*(__half2*)&u.x);
    float2 f1 = __half22float2(*(__half2*)&u.y);
    return make_float4(f0.x, f0.y, f1.x, f1.y);
}
__device__ __forceinline__ float2 ldh2(const __half* rowbase, int lane) {
    unsigned u = __ldg((const unsigned*)rowbase + lane);
    return __half22float2(*(__half2*)&u);
}

// out[i] = act(dinv[i] * sum_e dinv[src]*h[src] + b); self loop weight dinv[i].
__global__ void __launch_bounds__(256) agg1_kernel(const float* __restrict__ b1, int n) {
    int gw = (int)((blockIdx.x * blockDim.x + threadIdx.x) >> 5);
    if (gw >= n) return;
    const int lane = threadIdx.x & 31;
    if (lane == 0) g_fill[gw] = 0;          // restore zero-invariant
    const float di = g_dinv[gw];
    float ax, ay, az, aw;
    {
        float4 v = ldh4(g_h1 + (size_t)gw * HID, lane);
        ax = di * v.x; ay = di * v.y; az = di * v.z; aw = di * v.w;
    }
    int e = row_start(gw);
    const int end = row_start(gw + 1);
    for (; e + 4 <= end; e += 4) {
        int s0 = __ldg(&g_csr[e]),     s1 = __ldg(&g_csr[e + 1]);
        int s2 = __ldg(&g_csr[e + 2]), s3 = __ldg(&g_csr[e + 3]);
        float w0 = __ldg(&g_dinv[s0]), w1 = __ldg(&g_dinv[s1]);
        float w2 = __ldg(&g_dinv[s2]), w3 = __ldg(&g_dinv[s3]);
        float4 a = ldh4(g_h1 + (size_t)s0 * HID, lane);
        float4 b = ldh4(g_h1 + (size_t)s1 * HID, lane);
        float4 c = ldh4(g_h1 + (size_t)s2 * HID, lane);
        float4 d = ldh4(g_h1 + (size_t)s3 * HID, lane);
        ax += w0 * a.x; ay += w0 * a.y; az += w0 * a.z; aw += w0 * a.w;
        ax += w1 * b.x; ay += w1 * b.y; az += w1 * b.z; aw += w1 * b.w;
        ax += w2 * c.x; ay += w2 * c.y; az += w2 * c.z; aw += w2 * c.w;
        ax += w3 * d.x; ay += w3 * d.y; az += w3 * d.z; aw += w3 * d.w;
    }
    for (; e < end; ++e) {
        int s0 = __ldg(&g_csr[e]);
        float w0 = __ldg(&g_dinv[s0]);
        float4 a = ldh4(g_h1 + (size_t)s0 * HID, lane);
        ax += w0 * a.x; ay += w0 * a.y; az += w0 * a.z; aw += w0 * a.w;
    }
    float4 bb = *((const float4*)b1 + lane);
    float4 r;
    r.x = fmaxf(di * ax + bb.x, 0.f);
    r.y = fmaxf(di * ay + bb.y, 0.f);
    r.z = fmaxf(di * az + bb.z, 0.f);
    r.w = fmaxf(di * aw + bb.w, 0.f);
    *((float4*)(g_agg1 + (size_t)gw * HID) + lane) = r;
}

__global__ void __launch_bounds__(256) agg2_kernel(const float* __restrict__ b2,
                                                   float* __restrict__ out, int n) {
    int gw = (int)((blockIdx.x * blockDim.x + threadIdx.x) >> 5);
    if (gw >= n) return;
    const int lane = threadIdx.x & 31;
    const float di = g_dinv[gw];
    float ax, ay;
    {
        float2 v = ldh2(g_h2 + (size_t)gw * ZD, lane);
        ax = di * v.x; ay = di * v.y;
    }
    int e = row_start(gw);
    const int end = row_start(gw + 1);
    for (; e + 4 <= end; e += 4) {
        int s0 = __ldg(&g_csr[e]),     s1 = __ldg(&g_csr[e + 1]);
        int s2 = __ldg(&g_csr[e + 2]), s3 = __ldg(&g_csr[e + 3]);
        float w0 = __ldg(&g_dinv[s0]), w1 = __ldg(&g_dinv[s1]);
        float w2 = __ldg(&g_dinv[s2]), w3 = __ldg(&g_dinv[s3]);
        float2 a = ldh2(g_h2 + (size_t)s0 * ZD, lane);
        float2 b = ldh2(g_h2 + (size_t)s1 * ZD, lane);
        float2 c = ldh2(g_h2 + (size_t)s2 * ZD, lane);
        float2 d = ldh2(g_h2 + (size_t)s3 * ZD, lane);
        ax += w0 * a.x; ay += w0 * a.y;
        ax += w1 * b.x; ay += w1 * b.y;
        ax += w2 * c.x; ay += w2 * c.y;
        ax += w3 * d.x; ay += w3 * d.y;
    }
    for (; e < end; ++e) {
        int s0 = __ldg(&g_csr[e]);
        float w0 = __ldg(&g_dinv[s0]);
        float2 a = ldh2(g_h2 + (size_t)s0 * ZD, lane);
        ax += w0 * a.x; ay += w0 * a.y;
    }
    float2 bb = *((const float2*)b2 + lane);
    float2 r;
    r.x = di * ax + bb.x;
    r.y = di * ay + bb.y;
    *((float2*)(out + (size_t)gw * ZD) + lane) = r;
}

// ---------------- launch ----------------------------------------------------
extern "C" void kernel_launch(void* const* d_in, const int* in_sizes, int n_in,
                              void* d_out, int out_size) {
    const float* x  = (const float*)d_in[0];
    const int*   ei = (const int*)d_in[1];     // int32
    const float* W1 = (const float*)d_in[2];
    const float* b1 = (const float*)d_in[3];
    const float* W2 = (const float*)d_in[4];
    const float* b2 = (const float*)d_in[5];
    float*       out = (float*)d_out;

    const int N = in_sizes[0] / IN_CH;   // 50000
    const int E = in_sizes[1] / 2;       // 800000
    const int E2 = E / 2;
    const int* src = ei;
    const int* dst = ei + E;

    const int TB = 256;
    const int nb = (N + SCAN_B - 1) / SCAN_B;
    hist_kernel<<<(E2 + TB - 1) / TB, TB>>>(dst, E2);               // 0
    scan1_kernel<<<nb, SCAN_B>>>(N);                                // 1
    scan2_kernel<<<1, 32>>>(nb);                                    // 2
    gemm_mma_kernel<HID, 0><<<(N + 127) / 128, 256>>>(x, W1, N);    // 3 <- ncu slot
    scatter_kernel<<<(E2 + TB - 1) / TB, TB>>>(src, dst, E2);       // 4
    agg1_kernel<<<((N * 32) + TB - 1) / TB, TB>>>(b1, N);           // 5
    gemm_mma_kernel<ZD, 1><<<(N + 127) / 128, 256>>>(nullptr, W2, N); // 6
    agg2_kernel<<<((N * 32) + TB - 1) / TB, TB>>>(b2, out, N);      // 7
}